// round 5
// baseline (speedup 1.0000x reference)
#include <cuda_runtime.h>

// Problem constants
#define BB   2
#define SS   2048
#define EE   2048
#define HQ   32
#define HKV  8
#define DD   64
#define KVD  512
#define ATTN_SCALE 0.125f   // 1/sqrt(64)

// Scratch (device globals: allocation-free)
__device__ float g_q  [(long long)BB*SS*EE];    // (B,S,32,64)
__device__ float g_k  [(long long)BB*SS*KVD];   // (B,S,8,64)
__device__ float g_v  [(long long)BB*SS*KVD];
__device__ float g_ctx[(long long)BB*SS*EE];    // (B,S,32,64)

// ---------------------------------------------------------------------------
// Generic register-blocked fp32 GEMM core.
//   C[m,n] = scale * sum_k A[m,k]*Bop[k,n] + bias[n]
// TRANSB=false: W is (K x N) row-major, ldw = row stride.
// TRANSB=true : W is (N x K) row-major, ldw = row stride (i.e. C = A @ W^T).
// Block tile BM x BN, K-tile BK, per-thread TM x TN, (BM/TM)*(BN/TN) threads.
// ---------------------------------------------------------------------------
template<int BM, int BN, int BK, int TM, int TN, bool TRANSB>
__device__ __forceinline__ void gemm_core(
    const float* __restrict__ A, int lda,
    const float* __restrict__ W, int ldw,
    const float* __restrict__ bias, float scale,
    float* __restrict__ C, long long ldc,
    int K, int brow, int bcol)
{
    constexpr int NT = (BM / TM) * (BN / TN);
    __shared__ float As[BK][BM + 1];   // transposed, padded: conflict-free bcast reads
    __shared__ float Ws[BK][BN];       // unpadded: aligned float4 reads

    const int tid = threadIdx.x;
    const int tx = tid % (BN / TN);
    const int ty = tid / (BN / TN);

    float acc[TM][TN];
#pragma unroll
    for (int i = 0; i < TM; i++)
#pragma unroll
        for (int j = 0; j < TN; j++) acc[i][j] = 0.f;

    for (int k0 = 0; k0 < K; k0 += BK) {
        // --- load A tile (BM x BK), store transposed ---
#pragma unroll
        for (int idx = tid * 4; idx < BM * BK; idx += NT * 4) {
            int r = idx / BK, c = idx % BK;
            float4 v = *reinterpret_cast<const float4*>(
                A + (long long)(brow + r) * lda + k0 + c);
            As[c + 0][r] = v.x; As[c + 1][r] = v.y;
            As[c + 2][r] = v.z; As[c + 3][r] = v.w;
        }
        // --- load B tile ---
        if (TRANSB) {
            // W is N x K row-major: load rows of W (N dim), transpose into Ws[k][n]
#pragma unroll
            for (int idx = tid * 4; idx < BN * BK; idx += NT * 4) {
                int r = idx / BK, c = idx % BK;      // r: n index, c: k index
                float4 v = *reinterpret_cast<const float4*>(
                    W + (long long)(bcol + r) * ldw + k0 + c);
                Ws[c + 0][r] = v.x; Ws[c + 1][r] = v.y;
                Ws[c + 2][r] = v.z; Ws[c + 3][r] = v.w;
            }
        } else {
            // W is K x N row-major: straight copy
#pragma unroll
            for (int idx = tid * 4; idx < BK * BN; idx += NT * 4) {
                int r = idx / BN, c = idx % BN;
                *reinterpret_cast<float4*>(&Ws[r][c]) =
                    *reinterpret_cast<const float4*>(
                        W + (long long)(k0 + r) * ldw + bcol + c);
            }
        }
        __syncthreads();

#pragma unroll
        for (int kk = 0; kk < BK; kk++) {
            float a_reg[TM];
#pragma unroll
            for (int i = 0; i < TM; i++) a_reg[i] = As[kk][ty * TM + i];
            float b_reg[TN];
#pragma unroll
            for (int j4 = 0; j4 < TN; j4 += 4) {
                float4 t = *reinterpret_cast<const float4*>(&Ws[kk][tx * TN + j4]);
                b_reg[j4 + 0] = t.x; b_reg[j4 + 1] = t.y;
                b_reg[j4 + 2] = t.z; b_reg[j4 + 3] = t.w;
            }
#pragma unroll
            for (int i = 0; i < TM; i++)
#pragma unroll
                for (int j = 0; j < TN; j++)
                    acc[i][j] = fmaf(a_reg[i], b_reg[j], acc[i][j]);
        }
        __syncthreads();
    }

    // --- epilogue ---
    float breg[TN];
#pragma unroll
    for (int j = 0; j < TN; j++)
        breg[j] = bias ? bias[bcol + tx * TN + j] : 0.f;

#pragma unroll
    for (int i = 0; i < TM; i++) {
        long long rowoff = (long long)(brow + ty * TM + i) * ldc + bcol + tx * TN;
#pragma unroll
        for (int j4 = 0; j4 < TN; j4 += 4) {
            float4 o;
            o.x = acc[i][j4 + 0] * scale + breg[j4 + 0];
            o.y = acc[i][j4 + 1] * scale + breg[j4 + 1];
            o.z = acc[i][j4 + 2] * scale + breg[j4 + 2];
            o.w = acc[i][j4 + 3] * scale + breg[j4 + 3];
            *reinterpret_cast<float4*>(C + rowoff + j4) = o;
        }
    }
}

// ---------------------------------------------------------------------------
// Plain NN GEMM + bias (projections). Grid: (N/BN, M/BM).
// ---------------------------------------------------------------------------
template<int BM, int BN, int BK, int TM, int TN>
__global__ void __launch_bounds__(256)
gemm_nn_bias(const float* __restrict__ A, int lda,
             const float* __restrict__ W, int ldw,
             const float* __restrict__ bias,
             float* __restrict__ C, int ldc, int K)
{
    gemm_core<BM, BN, BK, TM, TN, false>(
        A, lda, W, ldw, bias, 1.0f, C, (long long)ldc, K,
        blockIdx.y * BM, blockIdx.x * BN);
}

// ---------------------------------------------------------------------------
// Scores: per (b,h) batched NT GEMM, C = scale * q @ k^T, written into d_out
// attn region. Grid: (S/BN, S/BM, B*HQ).
// ---------------------------------------------------------------------------
__global__ void __launch_bounds__(256)
scores_kernel(const float* __restrict__ q, const float* __restrict__ k,
              float* __restrict__ attn)
{
    const int z  = blockIdx.z;        // 0..63
    const int b  = z >> 5;
    const int h  = z & 31;
    const int hk = h >> 2;

    const float* Ab = q + (long long)b * SS * EE  + h  * DD;   // lda = EE
    const float* Wb = k + (long long)b * SS * KVD + hk * DD;   // ldb = KVD (N x K)
    float*       Cb = attn + (long long)z * SS * SS;           // ldc = SS

    gemm_core<128, 128, 16, 8, 8, true>(
        Ab, EE, Wb, KVD, nullptr, ATTN_SCALE, Cb, (long long)SS, DD,
        blockIdx.y * 128, blockIdx.x * 128);
}

// ---------------------------------------------------------------------------
// Row softmax in-place on the attn region. One block per row of 2048.
// ---------------------------------------------------------------------------
__global__ void __launch_bounds__(256)
softmax_kernel(float* __restrict__ P)
{
    float* row = P + (long long)blockIdx.x * SS;
    const int tid  = threadIdx.x;
    const int lane = tid & 31;
    const int warp = tid >> 5;

    float v[8];
    float m = -1e30f;
#pragma unroll
    for (int i = 0; i < 8; i++) {
        v[i] = row[tid + i * 256];
        m = fmaxf(m, v[i]);
    }
#pragma unroll
    for (int o = 16; o > 0; o >>= 1) m = fmaxf(m, __shfl_xor_sync(~0u, m, o));

    __shared__ float smax[8];
    __shared__ float ssum[8];
    if (lane == 0) smax[warp] = m;
    __syncthreads();
    m = smax[0];
#pragma unroll
    for (int w = 1; w < 8; w++) m = fmaxf(m, smax[w]);

    float s = 0.f;
#pragma unroll
    for (int i = 0; i < 8; i++) {
        v[i] = __expf(v[i] - m);
        s += v[i];
    }
#pragma unroll
    for (int o = 16; o > 0; o >>= 1) s += __shfl_xor_sync(~0u, s, o);
    if (lane == 0) ssum[warp] = s;
    __syncthreads();
    s = 0.f;
#pragma unroll
    for (int w = 0; w < 8; w++) s += ssum[w];

    const float inv = 1.0f / s;
#pragma unroll
    for (int i = 0; i < 8; i++) row[tid + i * 256] = v[i] * inv;
}

// ---------------------------------------------------------------------------
// P @ V: per (b,h) batched NN GEMM (K = 2048, N = 64) into context buffer.
// Grid: (1, S/BM, B*HQ).
// ---------------------------------------------------------------------------
__global__ void __launch_bounds__(256)
pv_kernel(const float* __restrict__ attn, const float* __restrict__ v,
          float* __restrict__ ctx)
{
    const int z  = blockIdx.z;
    const int b  = z >> 5;
    const int h  = z & 31;
    const int hk = h >> 2;

    const float* Ab = attn + (long long)z * SS * SS;           // lda = SS
    const float* Wb = v + (long long)b * SS * KVD + hk * DD;   // ldw = KVD (K x N)
    float*       Cb = ctx + (long long)b * SS * EE + h * DD;   // ldc = EE

    gemm_core<128, 64, 16, 8, 4, false>(
        Ab, SS, Wb, KVD, nullptr, 1.0f, Cb, (long long)EE, SS,
        blockIdx.y * 128, blockIdx.x * 64);
}

// ---------------------------------------------------------------------------
// Launch: out (B,S,E) fp32 first, then attn_weights (B,32,S,S) fp32.
// ---------------------------------------------------------------------------
extern "C" void kernel_launch(void* const* d_in, const int* in_sizes, int n_in,
                              void* d_out, int out_size)
{
    const float* query = (const float*)d_in[0];
    const float* key_  = (const float*)d_in[1];
    const float* value = (const float*)d_in[2];
    const float* Wq = (const float*)d_in[3];  const float* bq = (const float*)d_in[4];
    const float* Wk = (const float*)d_in[5];  const float* bk = (const float*)d_in[6];
    const float* Wv = (const float*)d_in[7];  const float* bv = (const float*)d_in[8];
    const float* Wo = (const float*)d_in[9];  const float* bo = (const float*)d_in[10];

    float* out  = (float*)d_out;
    float* attn = out + (long long)BB * SS * EE;   // attn_weights region

    float *qbuf, *kbuf, *vbuf, *ctx;
    cudaGetSymbolAddress((void**)&qbuf, g_q);
    cudaGetSymbolAddress((void**)&kbuf, g_k);
    cudaGetSymbolAddress((void**)&vbuf, g_v);
    cudaGetSymbolAddress((void**)&ctx,  g_ctx);

    const int M = BB * SS;   // 4096
    dim3 blk(256);

    // Q/K/V projections
    gemm_nn_bias<128,128,16,8,8><<<dim3(EE/128,  M/128), blk>>>(query, EE, Wq, EE,  bq, qbuf, EE,  EE);
    gemm_nn_bias<128,128,16,8,8><<<dim3(KVD/128, M/128), blk>>>(key_,  EE, Wk, KVD, bk, kbuf, KVD, EE);
    gemm_nn_bias<128,128,16,8,8><<<dim3(KVD/128, M/128), blk>>>(value, EE, Wv, KVD, bv, vbuf, KVD, EE);

    // Scores (pre-softmax) -> attn region of d_out
    scores_kernel<<<dim3(SS/128, SS/128, BB*HQ), blk>>>(qbuf, kbuf, attn);

    // Softmax in place (one block per row)
    softmax_kernel<<<(unsigned)((long long)BB*HQ*SS), blk>>>(attn);

    // P @ V -> context
    pv_kernel<<<dim3(1, SS/128, BB*HQ), blk>>>(attn, vbuf, ctx);

    // Output projection -> out region of d_out
    gemm_nn_bias<128,128,16,8,8><<<dim3(EE/128, M/128), blk>>>(ctx, EE, Wo, EE, bo, out, EE, EE);
}

// round 6
// speedup vs baseline: 1.7974x; 1.7974x over previous
#include <cuda_runtime.h>
#include <cstdint>

// Problem constants
#define BB   2
#define SS   2048
#define EE   2048
#define HQ   32
#define HKV  8
#define DD   64
#define KVD  512
#define ATTN_SCALE 0.125f   // 1/sqrt(64)

// Scratch (device globals: allocation-free)
__device__ float g_q  [(long long)BB*SS*EE];    // (B,S,32,64)
__device__ float g_k  [(long long)BB*SS*KVD];   // (B,S,8,64)
__device__ float g_v  [(long long)BB*SS*KVD];
__device__ float g_ctx[(long long)BB*SS*EE];    // (B,S,32,64)

// ---------------------------------------------------------------------------
// tf32 helpers
// ---------------------------------------------------------------------------
__device__ __forceinline__ uint32_t f2tf32(float x) {
    uint32_t u;
    asm volatile("cvt.rna.tf32.f32 %0, %1;" : "=r"(u) : "f"(x));
    return u;
}

__device__ __forceinline__ void mma_tf32(float c[4], const uint32_t a[4],
                                         const uint32_t b[2]) {
    asm volatile(
        "mma.sync.aligned.m16n8k8.row.col.f32.tf32.tf32.f32 "
        "{%0,%1,%2,%3}, {%4,%5,%6,%7}, {%8,%9}, {%0,%1,%2,%3};\n"
        : "+f"(c[0]), "+f"(c[1]), "+f"(c[2]), "+f"(c[3])
        : "r"(a[0]), "r"(a[1]), "r"(a[2]), "r"(a[3]), "r"(b[0]), "r"(b[1]));
}

// ---------------------------------------------------------------------------
// tf32 tensor-core GEMM core.
//   C[m,n] = scale * sum_k A[m,k]*Bop[k,n] + bias[n]
// TRANSB=false: W is (K x N) row-major, ldw = row stride.
// TRANSB=true : W is (N x K) row-major, ldw = row stride (C = A @ W^T).
// Block tile BM x BN, K-tile BK, warp tile WM x WN.
// Warp layout: (BM/WM) x (BN/WN) warps; warp tile = (WM/16)x(WN/8) m16n8k8 mmas.
// smem: As[BM][BK+4] (conflict-free for 8row x 4col fragment reads),
//       Bs[BK][BN+8] (conflict-free for 4row x 8col fragment reads).
// ---------------------------------------------------------------------------
template<int BM, int BN, int BK, int WM, int WN, bool TRANSB>
__device__ __forceinline__ void gemm_mma_core(
    const float* __restrict__ A, int lda,
    const float* __restrict__ W, int ldw,
    const float* __restrict__ bias, float scale,
    float* __restrict__ C, long long ldc,
    int K, int brow, int bcol)
{
    constexpr int NWM = BM / WM;
    constexpr int NWN = BN / WN;
    constexpr int NT  = NWM * NWN * 32;
    constexpr int MT  = WM / 16;     // m-subtiles per warp
    constexpr int NTT = WN / 8;      // n-subtiles per warp
    constexpr int ASTR = BK + 4;     // float stride (mult of 4)
    constexpr int BSTR = BN + 8;     // float stride (mult of 4)

    __shared__ float As[BM][ASTR];
    __shared__ float Bs[BK][BSTR];

    const int tid  = threadIdx.x;
    const int wid  = tid >> 5;
    const int lane = tid & 31;
    const int wm   = (wid / NWN) * WM;
    const int wn   = (wid % NWN) * WN;
    const int gid  = lane >> 2;   // 0..7
    const int tig  = lane & 3;    // 0..3

    float acc[MT][NTT][4];
#pragma unroll
    for (int i = 0; i < MT; i++)
#pragma unroll
        for (int j = 0; j < NTT; j++)
#pragma unroll
            for (int r = 0; r < 4; r++) acc[i][j][r] = 0.f;

    for (int k0 = 0; k0 < K; k0 += BK) {
        // --- load A tile (BM x BK), tf32-rounded ---
#pragma unroll
        for (int idx = tid * 4; idx < BM * BK; idx += NT * 4) {
            int r = idx / BK, c = idx % BK;
            float4 v = *reinterpret_cast<const float4*>(
                A + (long long)(brow + r) * lda + k0 + c);
            float4 t;
            t.x = __uint_as_float(f2tf32(v.x));
            t.y = __uint_as_float(f2tf32(v.y));
            t.z = __uint_as_float(f2tf32(v.z));
            t.w = __uint_as_float(f2tf32(v.w));
            *reinterpret_cast<float4*>(&As[r][c]) = t;
        }
        // --- load B tile ---
        if (TRANSB) {
            // W is N x K row-major: transpose into Bs[k][n]
#pragma unroll
            for (int idx = tid * 4; idx < BN * BK; idx += NT * 4) {
                int r = idx / BK, c = idx % BK;   // r: n, c: k
                float4 v = *reinterpret_cast<const float4*>(
                    W + (long long)(bcol + r) * ldw + k0 + c);
                Bs[c + 0][r] = __uint_as_float(f2tf32(v.x));
                Bs[c + 1][r] = __uint_as_float(f2tf32(v.y));
                Bs[c + 2][r] = __uint_as_float(f2tf32(v.z));
                Bs[c + 3][r] = __uint_as_float(f2tf32(v.w));
            }
        } else {
            // W is K x N row-major: straight copy
#pragma unroll
            for (int idx = tid * 4; idx < BK * BN; idx += NT * 4) {
                int r = idx / BN, c = idx % BN;
                float4 v = *reinterpret_cast<const float4*>(
                    W + (long long)(k0 + r) * ldw + bcol + c);
                float4 t;
                t.x = __uint_as_float(f2tf32(v.x));
                t.y = __uint_as_float(f2tf32(v.y));
                t.z = __uint_as_float(f2tf32(v.z));
                t.w = __uint_as_float(f2tf32(v.w));
                *reinterpret_cast<float4*>(&Bs[r][c]) = t;
            }
        }
        __syncthreads();

#pragma unroll
        for (int kk = 0; kk < BK; kk += 8) {
            uint32_t af[MT][4];
            uint32_t bf[NTT][2];
#pragma unroll
            for (int i = 0; i < MT; i++) {
                int r = wm + 16 * i + gid;
                af[i][0] = __float_as_uint(As[r    ][kk + tig    ]);
                af[i][1] = __float_as_uint(As[r + 8][kk + tig    ]);
                af[i][2] = __float_as_uint(As[r    ][kk + tig + 4]);
                af[i][3] = __float_as_uint(As[r + 8][kk + tig + 4]);
            }
#pragma unroll
            for (int j = 0; j < NTT; j++) {
                int c = wn + 8 * j + gid;
                bf[j][0] = __float_as_uint(Bs[kk + tig    ][c]);
                bf[j][1] = __float_as_uint(Bs[kk + tig + 4][c]);
            }
#pragma unroll
            for (int i = 0; i < MT; i++)
#pragma unroll
                for (int j = 0; j < NTT; j++)
                    mma_tf32(acc[i][j], af[i], bf[j]);
        }
        __syncthreads();
    }

    // --- epilogue: scale + bias, float2 stores ---
#pragma unroll
    for (int i = 0; i < MT; i++) {
        int r0 = brow + wm + 16 * i + gid;
#pragma unroll
        for (int j = 0; j < NTT; j++) {
            int c0 = bcol + wn + 8 * j + tig * 2;
            float b0 = bias ? bias[c0]     : 0.f;
            float b1 = bias ? bias[c0 + 1] : 0.f;
            float2 o0, o1;
            o0.x = acc[i][j][0] * scale + b0;
            o0.y = acc[i][j][1] * scale + b1;
            o1.x = acc[i][j][2] * scale + b0;
            o1.y = acc[i][j][3] * scale + b1;
            *reinterpret_cast<float2*>(C + (long long)r0 * ldc + c0)       = o0;
            *reinterpret_cast<float2*>(C + (long long)(r0 + 8) * ldc + c0) = o1;
        }
    }
}

// ---------------------------------------------------------------------------
// Projections (and output proj): plain NN GEMM + bias. Grid (N/128, M/128).
// ---------------------------------------------------------------------------
__global__ void __launch_bounds__(256)
gemm_nn_bias(const float* __restrict__ A, int lda,
             const float* __restrict__ W, int ldw,
             const float* __restrict__ bias,
             float* __restrict__ C, int ldc, int K)
{
    gemm_mma_core<128, 128, 32, 64, 32, false>(
        A, lda, W, ldw, bias, 1.0f, C, (long long)ldc, K,
        blockIdx.y * 128, blockIdx.x * 128);
}

// ---------------------------------------------------------------------------
// Scores: per (b,h) NT GEMM, C = scale * q @ k^T -> attn region of d_out.
// Grid: (S/128, S/128, B*HQ). K = 64.
// ---------------------------------------------------------------------------
__global__ void __launch_bounds__(256)
scores_kernel(const float* __restrict__ q, const float* __restrict__ k,
              float* __restrict__ attn)
{
    const int z  = blockIdx.z;
    const int b  = z >> 5;
    const int h  = z & 31;
    const int hk = h >> 2;

    const float* Ab = q + (long long)b * SS * EE  + h  * DD;
    const float* Wb = k + (long long)b * SS * KVD + hk * DD;
    float*       Cb = attn + (long long)z * SS * SS;

    gemm_mma_core<128, 128, 16, 64, 32, true>(
        Ab, EE, Wb, KVD, nullptr, ATTN_SCALE, Cb, (long long)SS, DD,
        blockIdx.y * 128, blockIdx.x * 128);
}

// ---------------------------------------------------------------------------
// P @ V: per (b,h) NN GEMM (K=2048, N=64) -> context. Grid (1, S/128, B*HQ).
// ---------------------------------------------------------------------------
__global__ void __launch_bounds__(256)
pv_kernel(const float* __restrict__ attn, const float* __restrict__ v,
          float* __restrict__ ctx)
{
    const int z  = blockIdx.z;
    const int b  = z >> 5;
    const int h  = z & 31;
    const int hk = h >> 2;

    const float* Ab = attn + (long long)z * SS * SS;
    const float* Wb = v + (long long)b * SS * KVD + hk * DD;
    float*       Cb = ctx + (long long)b * SS * EE + h * DD;

    gemm_mma_core<128, 64, 32, 32, 32, false>(
        Ab, SS, Wb, KVD, nullptr, 1.0f, Cb, (long long)EE, SS,
        blockIdx.y * 128, blockIdx.x * 64);
}

// ---------------------------------------------------------------------------
// Row softmax in-place, float4-vectorized. One block (256 thr) per 2048-row.
// ---------------------------------------------------------------------------
__global__ void __launch_bounds__(256)
softmax_kernel(float* __restrict__ P)
{
    float4* row = reinterpret_cast<float4*>(P + (long long)blockIdx.x * SS);
    const int tid  = threadIdx.x;
    const int lane = tid & 31;
    const int warp = tid >> 5;

    float4 v0 = row[tid];
    float4 v1 = row[tid + 256];

    float m = fmaxf(fmaxf(fmaxf(v0.x, v0.y), fmaxf(v0.z, v0.w)),
                    fmaxf(fmaxf(v1.x, v1.y), fmaxf(v1.z, v1.w)));
#pragma unroll
    for (int o = 16; o > 0; o >>= 1) m = fmaxf(m, __shfl_xor_sync(~0u, m, o));

    __shared__ float smax[8];
    __shared__ float ssum[8];
    if (lane == 0) smax[warp] = m;
    __syncthreads();
    m = smax[0];
#pragma unroll
    for (int w = 1; w < 8; w++) m = fmaxf(m, smax[w]);

    v0.x = __expf(v0.x - m); v0.y = __expf(v0.y - m);
    v0.z = __expf(v0.z - m); v0.w = __expf(v0.w - m);
    v1.x = __expf(v1.x - m); v1.y = __expf(v1.y - m);
    v1.z = __expf(v1.z - m); v1.w = __expf(v1.w - m);

    float s = v0.x + v0.y + v0.z + v0.w + v1.x + v1.y + v1.z + v1.w;
#pragma unroll
    for (int o = 16; o > 0; o >>= 1) s += __shfl_xor_sync(~0u, s, o);
    if (lane == 0) ssum[warp] = s;
    __syncthreads();
    s = 0.f;
#pragma unroll
    for (int w = 0; w < 8; w++) s += ssum[w];

    const float inv = 1.0f / s;
    v0.x *= inv; v0.y *= inv; v0.z *= inv; v0.w *= inv;
    v1.x *= inv; v1.y *= inv; v1.z *= inv; v1.w *= inv;
    row[tid]       = v0;
    row[tid + 256] = v1;
}

// ---------------------------------------------------------------------------
// Launch: out (B,S,E) fp32 first, then attn_weights (B,32,S,S) fp32.
// ---------------------------------------------------------------------------
extern "C" void kernel_launch(void* const* d_in, const int* in_sizes, int n_in,
                              void* d_out, int out_size)
{
    const float* query = (const float*)d_in[0];
    const float* key_  = (const float*)d_in[1];
    const float* value = (const float*)d_in[2];
    const float* Wq = (const float*)d_in[3];  const float* bq = (const float*)d_in[4];
    const float* Wk = (const float*)d_in[5];  const float* bk = (const float*)d_in[6];
    const float* Wv = (const float*)d_in[7];  const float* bv = (const float*)d_in[8];
    const float* Wo = (const float*)d_in[9];  const float* bo = (const float*)d_in[10];

    float* out  = (float*)d_out;
    float* attn = out + (long long)BB * SS * EE;

    float *qbuf, *kbuf, *vbuf, *ctx;
    cudaGetSymbolAddress((void**)&qbuf, g_q);
    cudaGetSymbolAddress((void**)&kbuf, g_k);
    cudaGetSymbolAddress((void**)&vbuf, g_v);
    cudaGetSymbolAddress((void**)&ctx,  g_ctx);

    const int M = BB * SS;   // 4096
    dim3 blk(256);

    // Q/K/V projections (tf32 tensor cores)
    gemm_nn_bias<<<dim3(EE/128,  M/128), blk>>>(query, EE, Wq, EE,  bq, qbuf, EE,  EE);
    gemm_nn_bias<<<dim3(KVD/128, M/128), blk>>>(key_,  EE, Wk, KVD, bk, kbuf, KVD, EE);
    gemm_nn_bias<<<dim3(KVD/128, M/128), blk>>>(value, EE, Wv, KVD, bv, vbuf, KVD, EE);

    // Scores (pre-softmax) -> attn region of d_out
    scores_kernel<<<dim3(SS/128, SS/128, BB*HQ), blk>>>(qbuf, kbuf, attn);

    // Softmax in place
    softmax_kernel<<<(unsigned)((long long)BB*HQ*SS), blk>>>(attn);

    // P @ V -> context
    pv_kernel<<<dim3(1, SS/128, BB*HQ), blk>>>(attn, vbuf, ctx);

    // Output projection -> out region of d_out
    gemm_nn_bias<<<dim3(EE/128, M/128), blk>>>(ctx, EE, Wo, EE, bo, out, EE, EE);
}